// round 16
// baseline (speedup 1.0000x reference)
#include <cuda_runtime.h>

#define CB 4
#define CC 96
#define CHh 128
#define CWw 128
#define CL (CHh*CWw)      // 16384
#define CK 2
#define CR 6
#define CO (2*CC)         // 192

#define NSEQ (CB*CK*CC)   // 768
#define TILE 2048
#define ITEMS 8
#define NTILE (CL/TILE)   // 8
#define NBLK (NSEQ*NTILE) // 6144

#define IN_SMEM (CC*66*8) // 50688 bytes: [96][66] ull pairs / overlay float[96][132]

typedef unsigned long long ull;

// ---------------- device scratch (allocation-free) ----------------
__device__ __align__(16) float  g_xc[CB*CC*CL];
__device__ __align__(16) float  g_z [CB*CC*CL];     // silu(z)
__device__ __align__(16) float  g_u [CB*CC*CL];     // post conv+silu
__device__ __align__(16) float  g_db8[CB*CK*CL*8];  // {dts[6], B, C} per (b,k,p)
__device__ __align__(16) float  g_y0[CB*CC*CL];
__device__ __align__(16) float  g_y1[CB*CC*CL];
__device__ __align__(16) ull    g_w1d[CC*CO];       // in_proj^T dup-packed [c][o] = {w,w}
__device__ __align__(16) float  g_wt2[CC*CC];       // out_proj^T [c][o]
__device__ __align__(16) float  g_wtx[CC*16];       // x_proj^T   [c][kd]
// decoupled-lookback state
__device__ float g_aggP[NBLK];
__device__ float g_aggS[NBLK];
__device__ float g_incl[NBLK];
__device__ int   g_flag[NBLK];

__device__ __forceinline__ float ex2f(float x){
    float y; asm("ex2.approx.f32 %0, %1;" : "=f"(y) : "f"(x)); return y;
}
__device__ __forceinline__ float lg2f(float x){
    float y; asm("lg2.approx.f32 %0, %1;" : "=f"(y) : "f"(x)); return y;
}
__device__ __forceinline__ float sigmoidf_(float x){
    return 1.f / (1.f + __expf(-x));
}
__device__ __forceinline__ ull packf2(float lo, float hi){
    ull r; asm("mov.b64 %0, {%1,%2};" : "=l"(r) : "f"(lo), "f"(hi)); return r;
}
__device__ __forceinline__ void unpackf2(ull v, float& lo, float& hi){
    asm("mov.b64 {%0,%1}, %2;" : "=f"(lo), "=f"(hi) : "l"(v));
}
__device__ __forceinline__ ull fmaf2(ull a, ull b, ull c){
    ull d; asm("fma.rn.f32x2 %0, %1, %2, %3;" : "=l"(d) : "l"(a), "l"(b), "l"(c)); return d;
}

// ---------------- K0a/b/c: weight prep + flag zero ----------------
__global__ void k_tr1(const float* __restrict__ w1){
    int t = blockIdx.x*256 + threadIdx.x;
    if (t < CO*CC){
        int o = t / CC, c = t % CC;
        float v = w1[t];
        g_w1d[c*CO + o] = packf2(v, v);
    }
}
__global__ void k_tr2(const float* __restrict__ w2){
    int t = blockIdx.x*256 + threadIdx.x;
    if (t < CC*CC){ int o = t / CC, c = t % CC; g_wt2[c*CC + o] = w2[t]; }
}
__global__ void k_tr3(const float* __restrict__ xw){
    int t = blockIdx.x*256 + threadIdx.x;
    if (t < 16*CC){ int kd = t / CC, c = t % CC; g_wtx[c*16 + kd] = xw[t]; }
    if (t < NBLK) g_flag[t] = 0;
}

// ---------------- K1: in_proj GEMM, uniform-weight / lane-distinct-x ----------------
// grid (CL/128, CB, 2 halves); 256 thr = 8 warps; warp = 12 o x 128 l.
// smem: xd[c][p] = {x[l0+p], x[l0+p+64]} ull, p in [0,64). Lane owns pairs p=lane, lane+32.
__global__ __launch_bounds__(256) void k_inproj(const float* __restrict__ x){
    extern __shared__ ull xd[];          // [CC][66]
    float* ysm = (float*)xd;             // epilogue overlay [CC][132]
    int b    = blockIdx.y;
    int half = blockIdx.z;
    int l0   = blockIdx.x * 128;
    int t    = threadIdx.x;
    int w    = t >> 5, lane = t & 31;

    for (int i = t; i < CC*64; i += 256){
        int c = i >> 6, p = i & 63;
        const float* xb = x + (b*CC + c)*CL + l0;
        xd[c*66 + p] = packf2(xb[p], xb[p + 64]);
    }
    __syncthreads();

    int o0 = half*96 + w*12;             // global weight column base (warp-uniform)

    ull acc[12][2];
    #pragma unroll
    for (int j = 0; j < 12; j++){ acc[j][0] = 0ull; acc[j][1] = 0ull; }

    #pragma unroll 2
    for (int c = 0; c < CC; c++){
        const ulonglong2* wp = (const ulonglong2*)&g_w1d[c*CO + o0];
        ulonglong2 q0 = wp[0], q1 = wp[1], q2 = wp[2], q3 = wp[3], q4 = wp[4], q5 = wp[5];
        ull pw[12] = {q0.x,q0.y, q1.x,q1.y, q2.x,q2.y, q3.x,q3.y, q4.x,q4.y, q5.x,q5.y};
        ull px0 = xd[c*66 + lane];
        ull px1 = xd[c*66 + lane + 32];
        #pragma unroll
        for (int j = 0; j < 12; j++){
            acc[j][0] = fmaf2(pw[j], px0, acc[j][0]);
            acc[j][1] = fmaf2(pw[j], px1, acc[j][1]);
        }
    }
    __syncthreads();

    // stage results: row = local o (w*12+j), cols: pair p -> (p, p+64)
    #pragma unroll
    for (int j = 0; j < 12; j++){
        int row = w*12 + j;
        #pragma unroll
        for (int q = 0; q < 2; q++){
            float lo, hi; unpackf2(acc[j][q], lo, hi);
            int p = lane + 32*q;
            ysm[row*132 + p]      = lo;
            ysm[row*132 + p + 64] = hi;
        }
    }
    __syncthreads();

    for (int i = t; i < CC*128; i += 256){
        int row = i >> 7, l = i & 127;
        float v = ysm[row*132 + l];
        int idx = (b*CC + row)*CL + l0 + l;
        if (half == 0) g_xc[idx] = v;
        else           g_z[idx]  = v * sigmoidf_(v);
    }
}

// ---------------- K2: depthwise 3x3 conv + bias + SiLU, 4-wide vectorized ----------------
__global__ void k_conv(const float* __restrict__ cw, const float* __restrict__ cb){
    int idx = blockIdx.x*256 + threadIdx.x;       // over B*C*H*(W/4)
    if (idx >= CB*CC*CHh*(CWw/4)) return;
    int w4 = idx & 31;
    int h  = (idx >> 5) & (CHh-1);
    int bc = idx >> 12;
    int c  = bc % CC;
    const float* src = g_xc + ((ull)bc << 14);

    float wl[9];
    #pragma unroll
    for (int j = 0; j < 9; j++) wl[j] = __ldg(&cw[c*9 + j]);
    float bv = __ldg(&cb[c]);
    float acc0 = bv, acc1 = bv, acc2 = bv, acc3 = bv;

    #pragma unroll
    for (int r = 0; r < 3; r++){
        int hh = h + r - 1;
        if (hh < 0 || hh >= CHh) continue;
        const float* row = src + hh*CWw + w4*4;
        float4 v = *(const float4*)row;
        float L = (w4 > 0)  ? row[-1] : 0.f;
        float R = (w4 < 31) ? row[4]  : 0.f;
        float wa = wl[r*3+0], wb = wl[r*3+1], wc2 = wl[r*3+2];
        acc0 = fmaf(wa, L,   acc0); acc0 = fmaf(wb, v.x, acc0); acc0 = fmaf(wc2, v.y, acc0);
        acc1 = fmaf(wa, v.x, acc1); acc1 = fmaf(wb, v.y, acc1); acc1 = fmaf(wc2, v.z, acc1);
        acc2 = fmaf(wa, v.y, acc2); acc2 = fmaf(wb, v.z, acc2); acc2 = fmaf(wc2, v.w, acc2);
        acc3 = fmaf(wa, v.z, acc3); acc3 = fmaf(wb, v.w, acc3); acc3 = fmaf(wc2, R,   acc3);
    }
    float4 o;
    o.x = acc0 * sigmoidf_(acc0);
    o.y = acc1 * sigmoidf_(acc1);
    o.z = acc2 * sigmoidf_(acc2);
    o.w = acc3 * sigmoidf_(acc3);
    *(float4*)(g_u + ((ull)bc << 14) + h*CWw + w4*4) = o;
}

// ---------------- K3: x_proj only (C->16 rows), write db8 ----------------
__global__ void k_proj(){
    __shared__ float usm[CC][65];
    int b  = blockIdx.y;
    int p0 = blockIdx.x * 64;
    int t  = threadIdx.x;

    for (int i = t; i < CC*64; i += 256){
        int c = i >> 6, pp = i & 63;
        usm[c][pp] = g_u[(b*CC + c)*CL + p0 + pp];
    }
    __syncthreads();

    int to = t & 3, tl = t >> 2;
    float acc0 = 0.f, acc1 = 0.f, acc2 = 0.f, acc3 = 0.f;
    #pragma unroll 4
    for (int c = 0; c < CC; c++){
        float xv = usm[c][tl];
        float4 wv = *(const float4*)&g_wtx[c*16 + to*4];
        acc0 = fmaf(wv.x, xv, acc0);
        acc1 = fmaf(wv.y, xv, acc1);
        acc2 = fmaf(wv.z, xv, acc2);
        acc3 = fmaf(wv.w, xv, acc3);
    }
    int k = to >> 1;
    *(float4*)&g_db8[(((b*CK + k)*CL) + p0 + tl)*8 + (to & 1)*4] =
        make_float4(acc0, acc1, acc2, acc3);
}

// ---------------- K4: decoupled-lookback single-pass scan ----------------
#define LOG2E 1.4426950408889634f
__global__ __launch_bounds__(256) void k_scan(const float* __restrict__ Alogs,
                                              const float* __restrict__ dtw,
                                              const float* __restrict__ dtb,
                                              const float* __restrict__ Dsp){
    int bid = blockIdx.x;
    int tt  = bid / NSEQ;
    int seq = bid - tt*NSEQ;
    int c = seq % CC;
    int k = (seq / CC) & 1;
    int b = seq / (CC*CK);
    int t = threadIdx.x;
    int w = t >> 5, lane = t & 31;

    float An = -__expf(__ldg(&Alogs[k*CC + c]));
    float Dv = __ldg(&Dsp[k*CC + c]);
    float dw[CR];
    #pragma unroll
    for (int r = 0; r < CR; r++) dw[r] = __ldg(&dtw[(k*CC + c)*CR + r]);
    float db = __ldg(&dtb[k*CC + c]);

    const float4* dbp = (const float4*)(g_db8 + (ull)(b*CK + k)*CL*8);
    const float*  up  = g_u + (b*CC + c)*CL;
    float*        yo  = (k ? g_y1 : g_y0) + (b*CC + c)*CL;

    __shared__ float4 sv[TILE + TILE/ITEMS];
    __shared__ float  sP[8], sS[8], sPe[8], sSe[8];
    __shared__ float  sHin;

    const unsigned FULL = 0xffffffffu;

    int T0 = tt * TILE;
    int P0 = k ? (CL - T0 - TILE) : T0;

    #pragma unroll
    for (int ii = 0; ii < TILE/256; ii++){
        int i = ii*256 + t;
        int e = k ? (TILE-1 - i) : i;
        int p = P0 + i;
        float4 d0 = dbp[p*2];
        float4 d1 = dbp[p*2 + 1];
        float uv  = up[p];
        float s = db;
        s = fmaf(dw[0], d0.x, s); s = fmaf(dw[1], d0.y, s);
        s = fmaf(dw[2], d0.z, s); s = fmaf(dw[3], d0.w, s);
        s = fmaf(dw[4], d1.x, s); s = fmaf(dw[5], d1.y, s);
        float lg2v = (s > 20.f) ? s*LOG2E : lg2f(1.f + ex2f(s*LOG2E));
        float a = ex2f(An * lg2v);
        float delta = 0.6931471805599453f * lg2v;
        sv[e + (e>>3)] = make_float4(a, delta * uv * d1.z, d1.w, Dv * uv);
    }
    __syncthreads();

    int base = t * 9;
    float P = 1.f, S = 0.f;
    #pragma unroll
    for (int i2 = 0; i2 < ITEMS; i2++){
        float4 v = sv[base + i2];
        S = fmaf(v.x, S, v.y);
        P *= v.x;
    }

    float Pi = P, Si = S;
    #pragma unroll
    for (int off = 1; off < 32; off <<= 1){
        float pp = __shfl_up_sync(FULL, Pi, off);
        float ss = __shfl_up_sync(FULL, Si, off);
        if (lane >= off){ Si = fmaf(ss, Pi, Si); Pi *= pp; }
    }
    float Pex = __shfl_up_sync(FULL, Pi, 1);
    float Sex = __shfl_up_sync(FULL, Si, 1);
    if (lane == 0){ Pex = 1.f; Sex = 0.f; }
    if (lane == 31){ sP[w] = Pi; sS[w] = Si; }
    __syncthreads();

    if (t == 0){
        volatile int*   vflag = g_flag;
        volatile float* vaggP = g_aggP;
        volatile float* vaggS = g_aggS;
        volatile float* vincl = g_incl;

        float cp = 1.f, cs = 0.f;
        #pragma unroll
        for (int ww = 0; ww < 8; ww++){
            sPe[ww] = cp; sSe[ww] = cs;
            float Pw = sP[ww], Sw = sS[ww];
            cs = fmaf(Pw, cs, Sw);
            cp = Pw * cp;
        }

        float h_in;
        if (tt == 0){
            h_in = 0.f;
            vincl[bid] = cs;
            __threadfence();
            vflag[bid] = 2;
        } else {
            vaggP[bid] = cp; vaggS[bid] = cs;
            __threadfence();
            vflag[bid] = 1;
            float Pr = 1.f, Sr = 0.f;
            int j = bid - NSEQ;
            while (true){
                int f;
                do { f = vflag[j]; } while (f == 0);
                __threadfence();
                if (f == 2){
                    h_in = fmaf(Pr, vincl[j], Sr);
                    break;
                }
                float Pa = vaggP[j], Sa = vaggS[j];
                Sr = fmaf(Pr, Sa, Sr);
                Pr = Pr * Pa;
                j -= NSEQ;
            }
            vincl[bid] = fmaf(cp, h_in, cs);
            __threadfence();
            vflag[bid] = 2;
        }
        sHin = h_in;
    }
    __syncthreads();

    float h_in = sHin;
    float hw = fmaf(sPe[w], h_in, sSe[w]);
    float h  = fmaf(Pex, hw, Sex);
    float yv[ITEMS];
    #pragma unroll
    for (int i2 = 0; i2 < ITEMS; i2++){
        float4 v = sv[base + i2];
        h = fmaf(v.x, h, v.y);
        yv[i2] = fmaf(h, v.z, v.w);
    }

    int sb = t * ITEMS;
    if (k == 0){
        float4* dst = (float4*)(yo + T0 + sb);
        dst[0] = make_float4(yv[0], yv[1], yv[2], yv[3]);
        dst[1] = make_float4(yv[4], yv[5], yv[6], yv[7]);
    } else {
        float4* dst = (float4*)(yo + (CL - T0 - sb - 8));
        dst[0] = make_float4(yv[7], yv[6], yv[5], yv[4]);
        dst[1] = make_float4(yv[3], yv[2], yv[1], yv[0]);
    }
}

// ---------------- K5: LN * silu(z) gate, out_proj GEMM (f32x2), scale ----------------
__global__ void k_out(const float* __restrict__ onw, const float* __restrict__ onb,
                      const float* __restrict__ sw, float* __restrict__ out){
    __shared__ float xsm[CC][68];
    __shared__ float red[4][64], red2[4][64];
    __shared__ float mu[64], rs[64];
    int b  = blockIdx.y;
    int l0 = blockIdx.x * 64;
    int t  = threadIdx.x;

    for (int i = t; i < CC*64; i += 256){
        int c = i >> 6, l = i & 63;
        int g = (b*CC + c)*CL + l0 + l;
        xsm[c][l] = g_y0[g] + g_y1[g];
    }
    __syncthreads();

    int col = t & 63, part = t >> 6;
    float s = 0.f, s2 = 0.f;
    for (int c = part; c < CC; c += 4){
        float v = xsm[c][col];
        s += v; s2 = fmaf(v, v, s2);
    }
    red[part][col] = s; red2[part][col] = s2;
    __syncthreads();
    if (t < 64){
        float m  = (red[0][t]+red[1][t]+red[2][t]+red[3][t]) * (1.f/CC);
        float q  = (red2[0][t]+red2[1][t]+red2[2][t]+red2[3][t]) * (1.f/CC);
        mu[t] = m;
        rs[t] = rsqrtf(q - m*m + 1e-5f);
    }
    __syncthreads();

    for (int i = t; i < CC*64; i += 256){
        int c = i >> 6, l = i & 63;
        float v = (xsm[c][l] - mu[l]) * rs[l] * __ldg(&onw[c]) + __ldg(&onb[c]);
        v *= g_z[(b*CC + c)*CL + l0 + l];
        xsm[c][l] = v;
    }
    __syncthreads();

    int to = t & 15, tl = t >> 4;
    int o0 = to * 6;
    int lb = tl * 4;
    ull acc[3][4];
    #pragma unroll
    for (int jj = 0; jj < 3; jj++)
        #pragma unroll
        for (int i = 0; i < 4; i++) acc[jj][i] = 0ull;

    #pragma unroll 4
    for (int c = 0; c < CC; c++){
        float4 xv = *(const float4*)&xsm[c][lb];
        const ull* wp = (const ull*)&g_wt2[c*CC + o0];
        ull pw0 = wp[0], pw1 = wp[1], pw2 = wp[2];
        ull px[4] = {packf2(xv.x,xv.x), packf2(xv.y,xv.y),
                     packf2(xv.z,xv.z), packf2(xv.w,xv.w)};
        #pragma unroll
        for (int i = 0; i < 4; i++){
            acc[0][i] = fmaf2(pw0, px[i], acc[0][i]);
            acc[1][i] = fmaf2(pw1, px[i], acc[1][i]);
            acc[2][i] = fmaf2(pw2, px[i], acc[2][i]);
        }
    }
    __syncthreads();

    #pragma unroll
    for (int jj = 0; jj < 3; jj++)
        #pragma unroll
        for (int i = 0; i < 4; i++){
            float lo, hi; unpackf2(acc[jj][i], lo, hi);
            xsm[o0 + 2*jj    ][lb + i] = lo;
            xsm[o0 + 2*jj + 1][lb + i] = hi;
        }
    __syncthreads();

    for (int i = t; i < CC*64; i += 256){
        int o = i >> 6, l = i & 63;
        out[(b*CC + o)*CL + l0 + l] = xsm[o][l] * __ldg(&sw[o]);
    }
}

// ---------------- launch ----------------
extern "C" void kernel_launch(void* const* d_in, const int* in_sizes, int n_in,
                              void* d_out, int out_size){
    const float* x         = (const float*)d_in[0];
    const float* in_proj_w = (const float*)d_in[1];
    const float* conv_w    = (const float*)d_in[2];
    const float* conv_b    = (const float*)d_in[3];
    const float* x_proj_w  = (const float*)d_in[4];
    const float* dt_proj_w = (const float*)d_in[5];
    const float* dt_proj_b = (const float*)d_in[6];
    const float* A_logs    = (const float*)d_in[7];
    const float* Ds        = (const float*)d_in[8];
    const float* onw       = (const float*)d_in[9];
    const float* onb       = (const float*)d_in[10];
    const float* out_projw = (const float*)d_in[11];
    const float* scale_w   = (const float*)d_in[12];
    float* out = (float*)d_out;

    cudaFuncSetAttribute(k_inproj, cudaFuncAttributeMaxDynamicSharedMemorySize, IN_SMEM);

    k_tr1<<<(CO*CC + 255)/256, 256>>>(in_proj_w);
    k_tr2<<<(CC*CC + 255)/256, 256>>>(out_projw);
    k_tr3<<<(NBLK + 255)/256, 256>>>(x_proj_w);

    dim3 gin(CL/128, CB, 2);
    k_inproj<<<gin, 256, IN_SMEM>>>(x);                    // launch index 3 -> profiled
    k_conv<<<(CB*CC*CHh*(CWw/4))/256, 256>>>(conv_w, conv_b);
    dim3 g1(CL/64, CB);
    k_proj<<<g1, 256>>>();
    k_scan<<<NBLK, 256>>>(A_logs, dt_proj_w, dt_proj_b, Ds);
    k_out<<<g1, 256>>>(onw, onb, scale_w, out);
}

// round 17
// speedup vs baseline: 1.2033x; 1.2033x over previous
#include <cuda_runtime.h>

#define CB 4
#define CC 96
#define CHh 128
#define CWw 128
#define CL (CHh*CWw)      // 16384
#define CK 2
#define CR 6
#define CO (2*CC)         // 192

#define GCH 4                        // channels per scan group
#define NGRP (CB*CK*(CC/GCH))        // 192
#define STILE 1024
#define SITEMS 4
#define NSTILE (CL/STILE)            // 16
#define SNBLK (NGRP*NSTILE)          // 3072
#define SVROW 1280                   // padded float2 row (SVPAD(1023)=1278)
#define SVPAD(e) ((e) + ((e)>>2))
#define SCAN_DYN ((GCH*SVROW*2 + STILE + 4*32 + 4)*4)

typedef unsigned long long ull;

// ---------------- device scratch (allocation-free) ----------------
__device__ __align__(16) float  g_xc[CB*CC*CL];
__device__ __align__(16) float  g_z [CB*CC*CL];     // silu(z)
__device__ __align__(16) float  g_u [CB*CC*CL];     // post conv+silu
__device__ __align__(16) float  g_db8[CB*CK*CL*8];  // {dts[6], B, C} per (b,k,p)
__device__ __align__(16) float  g_y0[CB*CC*CL];
__device__ __align__(16) float  g_y1[CB*CC*CL];
__device__ __align__(16) float  g_wt1[CC*CO];       // in_proj^T  [c][o]
__device__ __align__(16) float  g_wt2[CC*CC];       // out_proj^T [c][o]
__device__ __align__(16) float  g_wtx[CC*16];       // x_proj^T   [c][kd]
// decoupled-lookback state (per block x channel)
__device__ float g_aggP[SNBLK*GCH];
__device__ float g_aggS[SNBLK*GCH];
__device__ float g_incl[SNBLK*GCH];
__device__ int   g_flag[SNBLK];

__device__ __forceinline__ float ex2f(float x){
    float y; asm("ex2.approx.f32 %0, %1;" : "=f"(y) : "f"(x)); return y;
}
__device__ __forceinline__ float lg2f(float x){
    float y; asm("lg2.approx.f32 %0, %1;" : "=f"(y) : "f"(x)); return y;
}
__device__ __forceinline__ float sigmoidf_(float x){
    return 1.f / (1.f + __expf(-x));
}
__device__ __forceinline__ ull packf2(float lo, float hi){
    ull r; asm("mov.b64 %0, {%1,%2};" : "=l"(r) : "f"(lo), "f"(hi)); return r;
}
__device__ __forceinline__ void unpackf2(ull v, float& lo, float& hi){
    asm("mov.b64 {%0,%1}, %2;" : "=f"(lo), "=f"(hi) : "l"(v));
}
__device__ __forceinline__ ull fmaf2(ull a, ull b, ull c){
    ull d; asm("fma.rn.f32x2 %0, %1, %2, %3;" : "=l"(d) : "l"(a), "l"(b), "l"(c)); return d;
}

// ---------------- K0a/b/c: weight transposes + flag zero ----------------
__global__ void k_tr1(const float* __restrict__ w1){
    int t = blockIdx.x*256 + threadIdx.x;
    if (t < CO*CC){ int o = t / CC, c = t % CC; g_wt1[c*CO + o] = w1[t]; }
}
__global__ void k_tr2(const float* __restrict__ w2){
    int t = blockIdx.x*256 + threadIdx.x;
    if (t < CC*CC){ int o = t / CC, c = t % CC; g_wt2[c*CC + o] = w2[t]; }
}
__global__ void k_tr3(const float* __restrict__ xw){
    int t = blockIdx.x*256 + threadIdx.x;
    if (t < 16*CC){ int kd = t / CC, c = t % CC; g_wtx[c*16 + kd] = xw[t]; }
    if (t < SNBLK) g_flag[t] = 0;
}

// ---------------- K1: in_proj GEMM 192x96, 64-pos tiles (R13 form) ----------------
__global__ void k_inproj(const float* __restrict__ x){
    __shared__ float xsm[CC][68];
    int b  = blockIdx.y;
    int l0 = blockIdx.x * 64;
    int t  = threadIdx.x;

    for (int i = t; i < CC*64; i += 256){
        int c = i >> 6, l = i & 63;
        xsm[c][l] = x[(b*CC + c)*CL + l0 + l];
    }
    __syncthreads();

    int to = t & 15, tl = t >> 4;
    int o0 = to * 12;
    int lb = tl * 4;

    ull acc[6][4];
    #pragma unroll
    for (int jj = 0; jj < 6; jj++)
        #pragma unroll
        for (int i = 0; i < 4; i++) acc[jj][i] = 0ull;

    #pragma unroll 4
    for (int c = 0; c < CC; c++){
        float4 xv = *(const float4*)&xsm[c][lb];
        const ull* wp = (const ull*)&g_wt1[c*CO + o0];
        ull pw0 = wp[0], pw1 = wp[1], pw2 = wp[2], pw3 = wp[3], pw4 = wp[4], pw5 = wp[5];
        ull px[4] = {packf2(xv.x,xv.x), packf2(xv.y,xv.y),
                     packf2(xv.z,xv.z), packf2(xv.w,xv.w)};
        #pragma unroll
        for (int i = 0; i < 4; i++){
            acc[0][i] = fmaf2(pw0, px[i], acc[0][i]);
            acc[1][i] = fmaf2(pw1, px[i], acc[1][i]);
            acc[2][i] = fmaf2(pw2, px[i], acc[2][i]);
            acc[3][i] = fmaf2(pw3, px[i], acc[3][i]);
            acc[4][i] = fmaf2(pw4, px[i], acc[4][i]);
            acc[5][i] = fmaf2(pw5, px[i], acc[5][i]);
        }
    }
    __syncthreads();

    for (int half = 0; half < 2; half++){
        if ((to < 8) == (half == 0)){
            int ob = o0 - half*96;
            #pragma unroll
            for (int jj = 0; jj < 6; jj++)
                #pragma unroll
                for (int i = 0; i < 4; i++){
                    float lo, hi; unpackf2(acc[jj][i], lo, hi);
                    xsm[ob + 2*jj    ][lb + i] = lo;
                    xsm[ob + 2*jj + 1][lb + i] = hi;
                }
        }
        __syncthreads();
        for (int i = t; i < CC*64; i += 256){
            int row = i >> 6, l = i & 63;
            float v = xsm[row][l];
            int idx = (b*CC + row)*CL + l0 + l;
            if (half == 0) g_xc[idx] = v;
            else           g_z[idx]  = v * sigmoidf_(v);
        }
        __syncthreads();
    }
}

// ---------------- K2: depthwise 3x3 conv + bias + SiLU, 4-wide ----------------
__global__ void k_conv(const float* __restrict__ cw, const float* __restrict__ cb){
    int idx = blockIdx.x*256 + threadIdx.x;       // over B*C*H*(W/4)
    if (idx >= CB*CC*CHh*(CWw/4)) return;
    int w4 = idx & 31;
    int h  = (idx >> 5) & (CHh-1);
    int bc = idx >> 12;
    int c  = bc % CC;
    const float* src = g_xc + ((ull)bc << 14);

    float wl[9];
    #pragma unroll
    for (int j = 0; j < 9; j++) wl[j] = __ldg(&cw[c*9 + j]);
    float bv = __ldg(&cb[c]);
    float acc0 = bv, acc1 = bv, acc2 = bv, acc3 = bv;

    #pragma unroll
    for (int r = 0; r < 3; r++){
        int hh = h + r - 1;
        if (hh < 0 || hh >= CHh) continue;
        const float* row = src + hh*CWw + w4*4;
        float4 v = *(const float4*)row;
        float L = (w4 > 0)  ? row[-1] : 0.f;
        float R = (w4 < 31) ? row[4]  : 0.f;
        float wa = wl[r*3+0], wb = wl[r*3+1], wc2 = wl[r*3+2];
        acc0 = fmaf(wa, L,   acc0); acc0 = fmaf(wb, v.x, acc0); acc0 = fmaf(wc2, v.y, acc0);
        acc1 = fmaf(wa, v.x, acc1); acc1 = fmaf(wb, v.y, acc1); acc1 = fmaf(wc2, v.z, acc1);
        acc2 = fmaf(wa, v.y, acc2); acc2 = fmaf(wb, v.z, acc2); acc2 = fmaf(wc2, v.w, acc2);
        acc3 = fmaf(wa, v.z, acc3); acc3 = fmaf(wb, v.w, acc3); acc3 = fmaf(wc2, R,   acc3);
    }
    float4 o;
    o.x = acc0 * sigmoidf_(acc0);
    o.y = acc1 * sigmoidf_(acc1);
    o.z = acc2 * sigmoidf_(acc2);
    o.w = acc3 * sigmoidf_(acc3);
    *(float4*)(g_u + ((ull)bc << 14) + h*CWw + w4*4) = o;
}

// ---------------- K3: x_proj only (C->16 rows), write db8 ----------------
__global__ void k_proj(){
    __shared__ float usm[CC][65];
    int b  = blockIdx.y;
    int p0 = blockIdx.x * 64;
    int t  = threadIdx.x;

    for (int i = t; i < CC*64; i += 256){
        int c = i >> 6, pp = i & 63;
        usm[c][pp] = g_u[(b*CC + c)*CL + p0 + pp];
    }
    __syncthreads();

    int to = t & 3, tl = t >> 2;
    float acc0 = 0.f, acc1 = 0.f, acc2 = 0.f, acc3 = 0.f;
    #pragma unroll 4
    for (int c = 0; c < CC; c++){
        float xv = usm[c][tl];
        float4 wv = *(const float4*)&g_wtx[c*16 + to*4];
        acc0 = fmaf(wv.x, xv, acc0);
        acc1 = fmaf(wv.y, xv, acc1);
        acc2 = fmaf(wv.z, xv, acc2);
        acc3 = fmaf(wv.w, xv, acc3);
    }
    int k = to >> 1;
    *(float4*)&g_db8[(((b*CK + k)*CL) + p0 + tl)*8 + (to & 1)*4] =
        make_float4(acc0, acc1, acc2, acc3);
}

// ---------------- K4: channel-grouped decoupled-lookback scan ----------------
// block = (b, k, 4-channel group) x 1024-tile. bid = tt*NGRP + g (tile-major).
#define LOG2E 1.4426950408889634f
#define LN2   0.6931471805599453f
__global__ __launch_bounds__(256) void k_scan(const float* __restrict__ Alogs,
                                              const float* __restrict__ dtw,
                                              const float* __restrict__ dtb){
    extern __shared__ float ssm[];
    float2* sva = (float2*)ssm;                    // [GCH][SVROW] {a, x}
    float*  svc = ssm + GCH*SVROW*2;               // [STILE] C values (seq order)
    float*  sPw = svc + STILE;                     // [8 warps][GCH]
    float*  sSw = sPw + 8*GCH;
    float*  sPe = sSw + 8*GCH;
    float*  sSe = sPe + 8*GCH;
    float*  sHin= sSe + 8*GCH;                     // [GCH]

    int bid = blockIdx.x;
    int tt  = bid / NGRP;
    int g   = bid - tt*NGRP;
    int cg  = g % (CC/GCH);
    int k   = (g / (CC/GCH)) & 1;
    int b   = g / ((CC/GCH)*CK);
    int c0  = cg * GCH;
    int t   = threadIdx.x;
    int w   = t >> 5, lane = t & 31;
    const unsigned FULL = 0xffffffffu;

    // per-channel constants in registers (uniform L1 loads)
    float rdw[GCH][CR], rdb[GCH], rAn[GCH];
    #pragma unroll
    for (int ch = 0; ch < GCH; ch++){
        #pragma unroll
        for (int r = 0; r < CR; r++)
            rdw[ch][r] = __ldg(&dtw[(k*CC + c0 + ch)*CR + r]);
        rdb[ch] = __ldg(&dtb[k*CC + c0 + ch]);
        rAn[ch] = -__expf(__ldg(&Alogs[k*CC + c0 + ch]));
    }

    const float4* dbp = (const float4*)(g_db8 + (ull)(b*CK + k)*CL*8);
    const float*  up  = g_u + (b*CC + c0)*CL;
    float*        yo  = (k ? g_y1 : g_y0) + (b*CC + c0)*CL;

    int T0 = tt * STILE;
    int P0 = k ? (CL - T0 - STILE) : T0;

    // ---- phase 1: load db8 once, compute {a,x} for 4 channels ----
    #pragma unroll
    for (int ii = 0; ii < STILE/256; ii++){
        int i = ii*256 + t;                 // phys-local
        int e = k ? (STILE-1 - i) : i;      // seq-local
        int p = P0 + i;
        float4 d0 = dbp[p*2];
        float4 d1 = dbp[p*2 + 1];
        svc[e] = d1.w;
        float Bv = d1.z;
        #pragma unroll
        for (int ch = 0; ch < GCH; ch++){
            float s = rdb[ch];
            s = fmaf(rdw[ch][0], d0.x, s); s = fmaf(rdw[ch][1], d0.y, s);
            s = fmaf(rdw[ch][2], d0.z, s); s = fmaf(rdw[ch][3], d0.w, s);
            s = fmaf(rdw[ch][4], d1.x, s); s = fmaf(rdw[ch][5], d1.y, s);
            float lg2v = (s > 20.f) ? s*LOG2E : lg2f(1.f + ex2f(s*LOG2E));
            float a  = ex2f(rAn[ch] * lg2v);
            float uv = up[ch*CL + p];
            sva[ch*SVROW + SVPAD(e)] = make_float2(a, (LN2*lg2v) * uv * Bv);
        }
    }
    __syncthreads();

    // ---- phase 2: per-channel block scans ----
    int e0 = t * SITEMS;
    float Pex[GCH], Sex[GCH];
    #pragma unroll
    for (int ch = 0; ch < GCH; ch++){
        float P = 1.f, S = 0.f;
        #pragma unroll
        for (int i2 = 0; i2 < SITEMS; i2++){
            float2 v = sva[ch*SVROW + SVPAD(e0 + i2)];
            S = fmaf(v.x, S, v.y);
            P *= v.x;
        }
        #pragma unroll
        for (int off = 1; off < 32; off <<= 1){
            float pp = __shfl_up_sync(FULL, P, off);
            float ss = __shfl_up_sync(FULL, S, off);
            if (lane >= off){ S = fmaf(ss, P, S); P *= pp; }
        }
        float pe = __shfl_up_sync(FULL, P, 1);
        float se = __shfl_up_sync(FULL, S, 1);
        Pex[ch] = lane ? pe : 1.f;
        Sex[ch] = lane ? se : 0.f;
        if (lane == 31){ sPw[w*GCH + ch] = P; sSw[w*GCH + ch] = S; }
    }
    __syncthreads();

    // ---- lookback: lanes 0..GCH-1 cooperate, one channel each ----
    if (t < GCH){
        int ch = t;
        volatile int*   vflag = g_flag;
        volatile float* vaggP = g_aggP;
        volatile float* vaggS = g_aggS;
        volatile float* vincl = g_incl;

        float cp = 1.f, cs = 0.f;
        #pragma unroll
        for (int ww = 0; ww < 8; ww++){
            sPe[ww*GCH + ch] = cp; sSe[ww*GCH + ch] = cs;
            float Pw = sPw[ww*GCH + ch], Sw = sSw[ww*GCH + ch];
            cs = fmaf(Pw, cs, Sw);
            cp = Pw * cp;
        }

        float h_in;
        if (tt == 0){
            h_in = 0.f;
            vincl[bid*GCH + ch] = cs;
            __threadfence();
            __syncwarp(0xF);
            if (ch == 0) vflag[bid] = 2;
        } else {
            vaggP[bid*GCH + ch] = cp;
            vaggS[bid*GCH + ch] = cs;
            __threadfence();
            __syncwarp(0xF);
            if (ch == 0) vflag[bid] = 1;
            float Pr = 1.f, Sr = 0.f;
            int j = bid - NGRP;
            while (true){
                int f = 0;
                if (ch == 0){ do { f = vflag[j]; } while (f == 0); }
                f = __shfl_sync(0xF, f, 0);
                __threadfence();
                if (f == 2){
                    h_in = fmaf(Pr, vincl[j*GCH + ch], Sr);
                    break;
                }
                Sr = fmaf(Pr, vaggS[j*GCH + ch], Sr);
                Pr = Pr * vaggP[j*GCH + ch];
                j -= NGRP;
            }
            vincl[bid*GCH + ch] = fmaf(cp, h_in, cs);
            __threadfence();
            __syncwarp(0xF);
            if (ch == 0) vflag[bid] = 2;
        }
        sHin[ch] = h_in;
    }
    __syncthreads();

    // ---- final pass: y = h*C written back into sva[..].x ----
    float4 Cv = make_float4(svc[e0], svc[e0+1], svc[e0+2], svc[e0+3]);
    #pragma unroll
    for (int ch = 0; ch < GCH; ch++){
        float hw = fmaf(sPe[w*GCH + ch], sHin[ch], sSe[w*GCH + ch]);
        float h  = fmaf(Pex[ch], hw, Sex[ch]);
        float cc[4] = {Cv.x, Cv.y, Cv.z, Cv.w};
        #pragma unroll
        for (int i2 = 0; i2 < SITEMS; i2++){
            int m = ch*SVROW + SVPAD(e0 + i2);
            float2 v = sva[m];
            h = fmaf(v.x, h, v.y);
            sva[m].x = h * cc[i2];
        }
    }
    __syncthreads();

    // ---- coalesced stores: 4 consecutive phys per thread per channel ----
    int i4 = t * 4;
    #pragma unroll
    for (int ch = 0; ch < GCH; ch++){
        float yv[4];
        #pragma unroll
        for (int j = 0; j < 4; j++){
            int i = i4 + j;
            int e = k ? (STILE-1 - i) : i;
            yv[j] = sva[ch*SVROW + SVPAD(e)].x;
        }
        *(float4*)(yo + ch*CL + P0 + i4) = make_float4(yv[0], yv[1], yv[2], yv[3]);
    }
}

// ---------------- K5: (y0+y1+Du) LN * silu(z), out_proj GEMM, scale ----------------
__global__ void k_out(const float* __restrict__ onw, const float* __restrict__ onb,
                      const float* __restrict__ Dsp,
                      const float* __restrict__ sw, float* __restrict__ out){
    __shared__ float xsm[CC][68];
    __shared__ float red[4][64], red2[4][64];
    __shared__ float mu[64], rs[64];
    int b  = blockIdx.y;
    int l0 = blockIdx.x * 64;
    int t  = threadIdx.x;

    for (int i = t; i < CC*64; i += 256){
        int c = i >> 6, l = i & 63;
        int g = (b*CC + c)*CL + l0 + l;
        float dsum = __ldg(&Dsp[c]) + __ldg(&Dsp[CC + c]);
        xsm[c][l] = g_y0[g] + g_y1[g] + dsum * g_u[g];
    }
    __syncthreads();

    int col = t & 63, part = t >> 6;
    float s = 0.f, s2 = 0.f;
    for (int c = part; c < CC; c += 4){
        float v = xsm[c][col];
        s += v; s2 = fmaf(v, v, s2);
    }
    red[part][col] = s; red2[part][col] = s2;
    __syncthreads();
    if (t < 64){
        float m  = (red[0][t]+red[1][t]+red[2][t]+red[3][t]) * (1.f/CC);
        float q  = (red2[0][t]+red2[1][t]+red2[2][t]+red2[3][t]) * (1.f/CC);
        mu[t] = m;
        rs[t] = rsqrtf(q - m*m + 1e-5f);
    }
    __syncthreads();

    for (int i = t; i < CC*64; i += 256){
        int c = i >> 6, l = i & 63;
        float v = (xsm[c][l] - mu[l]) * rs[l] * __ldg(&onw[c]) + __ldg(&onb[c]);
        v *= g_z[(b*CC + c)*CL + l0 + l];
        xsm[c][l] = v;
    }
    __syncthreads();

    int to = t & 15, tl = t >> 4;
    int o0 = to * 6;
    int lb = tl * 4;
    ull acc[3][4];
    #pragma unroll
    for (int jj = 0; jj < 3; jj++)
        #pragma unroll
        for (int i = 0; i < 4; i++) acc[jj][i] = 0ull;

    #pragma unroll 4
    for (int c = 0; c < CC; c++){
        float4 xv = *(const float4*)&xsm[c][lb];
        const ull* wp = (const ull*)&g_wt2[c*CC + o0];
        ull pw0 = wp[0], pw1 = wp[1], pw2 = wp[2];
        ull px[4] = {packf2(xv.x,xv.x), packf2(xv.y,xv.y),
                     packf2(xv.z,xv.z), packf2(xv.w,xv.w)};
        #pragma unroll
        for (int i = 0; i < 4; i++){
            acc[0][i] = fmaf2(pw0, px[i], acc[0][i]);
            acc[1][i] = fmaf2(pw1, px[i], acc[1][i]);
            acc[2][i] = fmaf2(pw2, px[i], acc[2][i]);
        }
    }
    __syncthreads();

    #pragma unroll
    for (int jj = 0; jj < 3; jj++)
        #pragma unroll
        for (int i = 0; i < 4; i++){
            float lo, hi; unpackf2(acc[jj][i], lo, hi);
            xsm[o0 + 2*jj    ][lb + i] = lo;
            xsm[o0 + 2*jj + 1][lb + i] = hi;
        }
    __syncthreads();

    for (int i = t; i < CC*64; i += 256){
        int o = i >> 6, l = i & 63;
        out[(b*CC + o)*CL + l0 + l] = xsm[o][l] * __ldg(&sw[o]);
    }
}

// ---------------- launch ----------------
extern "C" void kernel_launch(void* const* d_in, const int* in_sizes, int n_in,
                              void* d_out, int out_size){
    const float* x         = (const float*)d_in[0];
    const float* in_proj_w = (const float*)d_in[1];
    const float* conv_w    = (const float*)d_in[2];
    const float* conv_b    = (const float*)d_in[3];
    const float* x_proj_w  = (const float*)d_in[4];
    const float* dt_proj_w = (const float*)d_in[5];
    const float* dt_proj_b = (const float*)d_in[6];
    const float* A_logs    = (const float*)d_in[7];
    const float* Ds        = (const float*)d_in[8];
    const float* onw       = (const float*)d_in[9];
    const float* onb       = (const float*)d_in[10];
    const float* out_projw = (const float*)d_in[11];
    const float* scale_w   = (const float*)d_in[12];
    float* out = (float*)d_out;

    k_tr1<<<(CO*CC + 255)/256, 256>>>(in_proj_w);
    k_tr2<<<(CC*CC + 255)/256, 256>>>(out_projw);
    k_tr3<<<(SNBLK + 255)/256, 256>>>(x_proj_w);

    dim3 g1(CL/64, CB);
    k_inproj<<<g1, 256>>>(x);                              // launch index 3 -> profiled
    k_conv<<<(CB*CC*CHh*(CWw/4))/256, 256>>>(conv_w, conv_b);
    k_proj<<<g1, 256>>>();
    k_scan<<<SNBLK, 256, SCAN_DYN>>>(A_logs, dt_proj_w, dt_proj_b);
    k_out<<<g1, 256>>>(onw, onb, Ds, scale_w, out);
}